// round 12
// baseline (speedup 1.0000x reference)
#include <cuda_runtime.h>
#include <cuda_bf16.h>
#include <math.h>
#include <stdint.h>
#include <stdio.h>

#define BB 16
#define SS 1024
#define DD 512
#define NN 2048

#define RCTAS 64
#define RTHREADS 512   // 16 warps; each half-warp: 1 row x 16 batches

// ---------------- device scratch ----------------
__device__ float2   g_ent[(size_t)NN * NN];        // padded CSR entries {val, idx-bits}
__device__ int      g_nnz[NN];
__device__ int      g_rowptr[NN + 1];
__device__ float    g_state0[NN * BB];             // transposed initial state [n][b]
__device__ float    g_drive[(size_t)SS * NN * BB]; // [s][n][b]; overwritten with states
__device__ unsigned g_cnt;
__device__ unsigned g_flag;
__device__ unsigned g_prog[8];                     // per-128-step-chunk GEMM progress
__device__ unsigned long long g_ts[8];

// ---------------- helpers ----------------
__device__ __forceinline__ void ts_mark(int i) {
    if (blockIdx.x == 0 && blockIdx.y == 0 && threadIdx.x == 0) {
        unsigned long long t;
        asm volatile("mov.u64 %0, %%globaltimer;" : "=l"(t));
        g_ts[i] = t;
    }
}
__device__ __forceinline__ void mma_bf16(float* d, const uint32_t* a, const uint32_t* b) {
    asm volatile(
        "mma.sync.aligned.m16n8k16.row.col.f32.bf16.bf16.f32 "
        "{%0,%1,%2,%3}, {%4,%5,%6,%7}, {%8,%9}, {%0,%1,%2,%3};"
        : "+f"(d[0]), "+f"(d[1]), "+f"(d[2]), "+f"(d[3])
        : "r"(a[0]), "r"(a[1]), "r"(a[2]), "r"(a[3]), "r"(b[0]), "r"(b[1]));
}
__device__ __forceinline__ void split2(float x, float y, uint32_t& h, uint32_t& l) {
    __nv_bfloat16 hx = __float2bfloat16_rn(x);
    __nv_bfloat16 hy = __float2bfloat16_rn(y);
    __nv_bfloat16 lx = __float2bfloat16_rn(x - __bfloat162float(hx));
    __nv_bfloat16 ly = __float2bfloat16_rn(y - __bfloat162float(hy));
    __nv_bfloat162 ph = __halves2bfloat162(hx, hy);
    __nv_bfloat162 pl = __halves2bfloat162(lx, ly);
    h = *reinterpret_cast<uint32_t*>(&ph);
    l = *reinterpret_cast<uint32_t*>(&pl);
}

// ---------------- prep kernels ----------------
__global__ void init_kernel(const float* __restrict__ init_state) {
    ts_mark(0);
    int i = blockIdx.x * blockDim.x + threadIdx.x;
    if (i == 0) { g_cnt = 0u; g_flag = 0u; }
    if (i < 8) g_prog[i] = 0u;
    if (i < NN * BB) {
        int b = i & (BB - 1);
        int n = i >> 4;
        g_state0[i] = init_state[(size_t)b * NN + n];
    }
}

__global__ void count_kernel(const float* __restrict__ W) {
    ts_mark(1);
    int gw   = (blockIdx.x * blockDim.x + threadIdx.x) >> 5;
    int lane = threadIdx.x & 31;
    if (gw >= NN) return;
    const float* row = W + (size_t)gw * NN;
    int c = 0;
    for (int m0 = 0; m0 < NN; m0 += 32) {
        float w = row[m0 + lane];
        c += __popc(__ballot_sync(0xffffffffu, w != 0.0f));
    }
    if (lane == 0) g_nnz[gw] = (c + 15) & ~15;
}

__global__ void scan_kernel() {
    ts_mark(2);
    __shared__ int sb[2][NN];
    int t = threadIdx.x;
    sb[0][t] = g_nnz[t];
    sb[0][t + 1024] = g_nnz[t + 1024];
    __syncthreads();
    int cur = 0;
    for (int d = 1; d < NN; d <<= 1) {
        for (int k = t; k < NN; k += 1024) {
            int v = sb[cur][k];
            if (k >= d) v += sb[cur][k - d];
            sb[cur ^ 1][k] = v;
        }
        __syncthreads();
        cur ^= 1;
    }
    if (t == 0) g_rowptr[0] = 0;
    g_rowptr[t + 1] = sb[cur][t];
    g_rowptr[t + 1 + 1024] = sb[cur][t + 1024];
}

__global__ void fill_kernel(const float* __restrict__ W) {
    ts_mark(3);
    int gw   = (blockIdx.x * blockDim.x + threadIdx.x) >> 5;
    int lane = threadIdx.x & 31;
    if (gw >= NN) return;
    const float* row = W + (size_t)gw * NN;
    int p = g_rowptr[gw];
    for (int m0 = 0; m0 < NN; m0 += 32) {
        float w = row[m0 + lane];
        unsigned msk = __ballot_sync(0xffffffffu, w != 0.0f);
        if (w != 0.0f) {
            int off = p + __popc(msk & ((1u << lane) - 1u));
            g_ent[off] = make_float2(w, __int_as_float(m0 + lane));
        }
        p += __popc(msk);
    }
    int end = g_rowptr[gw + 1];
    for (int q = p + lane; q < end; q += 32)
        g_ent[q] = make_float2(0.0f, __int_as_float(0));
}

// ---------------- bf16 3-split mma.sync drive GEMM (s-chunk-major order) ----------------
#define SMU 20

__global__ void __launch_bounds__(256) drive_gemm_bf16(
    const float* __restrict__ X, const float* __restrict__ FB,
    const float* __restrict__ Win, const float* __restrict__ Wfb)
{
    ts_mark(4);
    __shared__ uint32_t Ah[128 * SMU], Al[128 * SMU], Bh[128 * SMU], Bl[128 * SMU];

    int tid  = threadIdx.x;
    int wid  = tid >> 5, lane = tid & 31;
    int gid  = lane >> 2, tig = lane & 3;
    int wm   = wid & 1, wn = wid >> 1;

    // s-chunk-major remap: y in [0,128) -> sChunk = y>>4, bIdx = y&15.
    // All 256 CTAs (16 bIdx x 16 col-tiles) of sChunk k occupy blockIdx range [k*256,(k+1)*256).
    int sChunk = blockIdx.y >> 4;
    int bIdx   = blockIdx.y & 15;
    int rowBase = bIdx * 1024 + sChunk * 128;
    int colBase = blockIdx.x * 128;

    int lr = tid >> 1;
    int lh = (tid & 1) * 4;

    const float* Aarr[2] = {X, FB};
    const float* Barr[2] = {Win, Wfb};

    float acc[4][4][4];
#pragma unroll
    for (int i = 0; i < 4; i++)
#pragma unroll
        for (int j = 0; j < 4; j++)
#pragma unroll
            for (int k = 0; k < 4; k++) acc[i][j][k] = 0.0f;

    float4 ra[4], rb[4];
#pragma unroll
    for (int j = 0; j < 4; j++) {
        ra[j] = __ldg((const float4*)(X   + (size_t)(rowBase + lr) * DD) + lh + j);
        rb[j] = __ldg((const float4*)(Win + (size_t)(colBase + lr) * DD) + lh + j);
    }

    const int NCHUNK = 32;
    for (int kt = 0; kt < NCHUNK; kt++) {
        __syncthreads();
#pragma unroll
        for (int j = 0; j < 4; j++) {
            int c4 = lh + j;
            int ui = lr * SMU + c4 * 2;
            uint32_t h0, l0, h1, l1;
            split2(ra[j].x, ra[j].y, h0, l0);
            split2(ra[j].z, ra[j].w, h1, l1);
            *(uint2*)&Ah[ui] = make_uint2(h0, h1);
            *(uint2*)&Al[ui] = make_uint2(l0, l1);
            split2(rb[j].x, rb[j].y, h0, l0);
            split2(rb[j].z, rb[j].w, h1, l1);
            *(uint2*)&Bh[ui] = make_uint2(h0, h1);
            *(uint2*)&Bl[ui] = make_uint2(l0, l1);
        }
        __syncthreads();

        if (kt + 1 < NCHUNK) {
            int nk = kt + 1;
            const float* A  = Aarr[nk >> 4];
            const float* Bm = Barr[nk >> 4];
            int kb = (nk & 15) * 8;
#pragma unroll
            for (int j = 0; j < 4; j++) {
                ra[j] = __ldg((const float4*)(A  + (size_t)(rowBase + lr) * DD) + kb + lh + j);
                rb[j] = __ldg((const float4*)(Bm + (size_t)(colBase + lr) * DD) + kb + lh + j);
            }
        }

#pragma unroll
        for (int ks = 0; ks < 2; ks++) {
            uint32_t bh[4][2], bl[4][2];
#pragma unroll
            for (int nt = 0; nt < 4; nt++) {
                int r = (wn * 32 + nt * 8 + gid) * SMU + ks * 8;
                bh[nt][0] = Bh[r + tig];
                bh[nt][1] = Bh[r + tig + 4];
                bl[nt][0] = Bl[r + tig];
                bl[nt][1] = Bl[r + tig + 4];
            }
#pragma unroll
            for (int mt = 0; mt < 4; mt++) {
                int r1 = (wm * 64 + mt * 16 + gid) * SMU + ks * 8;
                int r2 = r1 + 8 * SMU;
                uint32_t ah[4], al[4];
                ah[0] = Ah[r1 + tig]; ah[1] = Ah[r2 + tig];
                ah[2] = Ah[r1 + tig + 4]; ah[3] = Ah[r2 + tig + 4];
                al[0] = Al[r1 + tig]; al[1] = Al[r2 + tig];
                al[2] = Al[r1 + tig + 4]; al[3] = Al[r2 + tig + 4];
#pragma unroll
                for (int nt = 0; nt < 4; nt++) {
                    mma_bf16(acc[mt][nt], ah, bh[nt]);
                    mma_bf16(acc[mt][nt], ah, bl[nt]);
                    mma_bf16(acc[mt][nt], al, bh[nt]);
                }
            }
        }
    }

#pragma unroll
    for (int mt = 0; mt < 4; mt++) {
#pragma unroll
        for (int half = 0; half < 2; half++) {
            int m = rowBase + wm * 64 + mt * 16 + gid + half * 8;
            int b = m >> 10, s = m & 1023;
            size_t base = ((size_t)s * NN) * BB + b;
#pragma unroll
            for (int nt = 0; nt < 4; nt++) {
                int n = colBase + wn * 32 + nt * 8 + tig * 2;
                g_drive[base + (size_t)n * BB]       = acc[mt][nt][half * 2];
                g_drive[base + (size_t)(n + 1) * BB] = acc[mt][nt][half * 2 + 1];
            }
        }
    }

    // progress: this CTA's 128 s-values of chunk sChunk are written
    __threadfence();
    __syncthreads();
    if (tid == 0) atomicAdd(&g_prog[sChunk], 1u);
}

// ---------------- persistent recurrence (overlapped with GEMM) ----------------
__global__ void __launch_bounds__(RTHREADS, 1) recur_kernel() {
    ts_mark(5);
    int tid  = threadIdx.x;
    int w    = tid >> 5;
    int lane = tid & 31;
    int b    = lane & 15;
    int rsel = lane >> 4;
    int row  = blockIdx.x * (RTHREADS / 16) + w * 2 + rsel;

    int start = g_rowptr[row];
    int len   = g_rowptr[row + 1] - start;   // multiple of 16
    const float2* ent = g_ent + start;

    // wait for GEMM chunk 0
    if (tid == 0) {
        unsigned v;
        do {
            asm volatile("ld.acquire.gpu.global.u32 %0, [%1];"
                         : "=r"(v) : "l"(&g_prog[0]) : "memory");
        } while (v < 256u);
    }
    __syncthreads();

    const float* cur = g_state0;
    float drv = __ldcg(&g_drive[(row << 4) + b]);

    for (int s = 0; s < SS; ++s) {
        float acc = drv;
        for (int j = 0; j < len; j += 16) {
#pragma unroll
            for (int u = 0; u < 16; u++) {
                float2 e = ent[j + u];
                float sv = __ldcg(cur + ((__float_as_int(e.y) << 4) + b));
                acc = fmaf(e.x, sv, acc);
            }
        }
        float ns = tanhf(acc);
        float* d = g_drive + (size_t)s * (NN * BB);
        d[(row << 4) + b] = ns;

        bool cross = ((s + 1) & 127) == 0;       // next step enters a new GEMM chunk
        if (s + 1 < SS && !cross)                // prefetch next drive behind barrier
            drv = __ldcg(&g_drive[(size_t)(s + 1) * (NN * BB) + (row << 4) + b]);

        __syncthreads();
        if (s + 1 < SS) {
            if (tid == 0) {
                unsigned arr;
                asm volatile("atom.acq_rel.gpu.global.add.u32 %0, [%1], %2;"
                             : "=r"(arr) : "l"(&g_cnt), "r"(1u) : "memory");
                unsigned target = (unsigned)RCTAS * (unsigned)(s + 1);
                if (arr == target - 1u) {
                    asm volatile("st.release.gpu.global.u32 [%0], %1;"
                                 :: "l"(&g_flag), "r"((unsigned)(s + 1)) : "memory");
                } else {
                    unsigned v;
                    do {
                        asm volatile("ld.acquire.gpu.global.u32 %0, [%1];"
                                     : "=r"(v) : "l"(&g_flag) : "memory");
                    } while (v < (unsigned)(s + 1));
                }
                if (cross) {   // rare (7x): wait for GEMM to finish next chunk
                    unsigned v;
                    do {
                        asm volatile("ld.acquire.gpu.global.u32 %0, [%1];"
                                     : "=r"(v) : "l"(&g_prog[(s + 1) >> 7]) : "memory");
                    } while (v < 256u);
                }
            }
            __syncthreads();
            if (cross)
                drv = __ldcg(&g_drive[(size_t)(s + 1) * (NN * BB) + (row << 4) + b]);
        }
        cur = d;
    }
}

// ---------------- final transpose: g_drive[s][n][b] -> out[b][s][n] ----------------
#define TSB 8
#define TNB 64
__global__ void __launch_bounds__(256) transpose_kernel(float* __restrict__ out) {
    ts_mark(6);
    __shared__ float smt[TSB * TNB * 17];
    int s0 = blockIdx.y * TSB, n0 = blockIdx.x * TNB;
    for (int i = threadIdx.x; i < TSB * TNB * BB; i += 256) {
        int b = i & 15, nl = (i >> 4) & 63, sl = i >> 10;
        smt[(sl * TNB + nl) * 17 + b] =
            g_drive[((size_t)(s0 + sl) * NN + n0 + nl) * BB + b];
    }
    __syncthreads();
    for (int i = threadIdx.x; i < TSB * TNB * BB; i += 256) {
        int nl = i & 63, sl = (i >> 6) & 7, b = i >> 9;
        out[((size_t)b * SS + s0 + sl) * NN + n0 + nl] =
            smt[(sl * TNB + nl) * 17 + b];
    }
}

// ---------------- timing reporter ----------------
__global__ void report_kernel() {
    unsigned long long t;
    asm volatile("mov.u64 %0, %%globaltimer;" : "=l"(t));
    g_ts[7] = t;
    unsigned long long* ts = g_ts;
    printf("KTIME(us) init=%llu count=%llu scan=%llu fill=%llu gemm_start_to_recur_start=%llu recur_to_trans=%llu trans=%llu\n",
           (ts[1] - ts[0]) / 1000ull, (ts[2] - ts[1]) / 1000ull,
           (ts[3] - ts[2]) / 1000ull, (ts[4] - ts[3]) / 1000ull,
           (ts[5] - ts[4]) / 1000ull, (ts[6] - ts[5]) / 1000ull,
           (ts[7] - ts[6]) / 1000ull);
}

// ---------------- launch ----------------
extern "C" void kernel_launch(void* const* d_in, const int* in_sizes, int n_in,
                              void* d_out, int out_size) {
    const float* x    = (const float*)d_in[0];
    const float* fb   = (const float*)d_in[1];
    const float* init = (const float*)d_in[2];
    const float* Wres = (const float*)d_in[3];
    const float* Win  = (const float*)d_in[4];
    const float* Wfb  = (const float*)d_in[5];
    float* out = (float*)d_out;

    // Lazily created on the first (non-captured, correctness) call; reused during capture.
    static cudaStream_t side = nullptr;
    static cudaEvent_t ev_fork = nullptr, ev_join = nullptr;
    if (side == nullptr) {
        cudaStreamCreateWithFlags(&side, cudaStreamNonBlocking);
        cudaEventCreateWithFlags(&ev_fork, cudaEventDisableTiming);
        cudaEventCreateWithFlags(&ev_join, cudaEventDisableTiming);
    }

    init_kernel<<<(NN * BB + 255) / 256, 256>>>(init);
    count_kernel<<<64, 1024>>>(Wres);
    scan_kernel<<<1, 1024>>>();
    fill_kernel<<<64, 1024>>>(Wres);

    // fork: recurrence runs on side stream, overlapping the GEMM on the main stream
    cudaEventRecord(ev_fork, 0);
    cudaStreamWaitEvent(side, ev_fork, 0);
    recur_kernel<<<RCTAS, RTHREADS, 0, side>>>();
    cudaEventRecord(ev_join, side);

    drive_gemm_bf16<<<dim3(NN / 128, 128), 256>>>(x, fb, Win, Wfb);

    // join: transpose needs both GEMM (program order) and recurrence (event) done
    cudaStreamWaitEvent(0, ev_join, 0);
    transpose_kernel<<<dim3(NN / TNB, SS / TSB), 256>>>(out);
    report_kernel<<<1, 1>>>();
}

// round 13
// speedup vs baseline: 1.0691x; 1.0691x over previous
#include <cuda_runtime.h>
#include <cuda_bf16.h>
#include <math.h>
#include <stdint.h>
#include <stdio.h>

#define BB 16
#define SS 1024
#define DD 512
#define NN 2048

#define RCTAS 64
#define RTHREADS 512   // 16 warps; each half-warp: 1 row x 16 batches

// ---------------- device scratch ----------------
__device__ float2   g_ent[(size_t)NN * NN];        // padded CSR entries {val, idx-bits}
__device__ int      g_nnz[NN];
__device__ int      g_rowptr[NN + 1];
__device__ float    g_state0[NN * BB];             // transposed initial state [n][b]
__device__ float    g_drive[(size_t)SS * NN * BB]; // [s][n][b]; overwritten with states
__device__ unsigned g_cnt;
__device__ unsigned g_flag;
__device__ unsigned g_prog[8];                     // per-128-step-chunk GEMM progress
__device__ unsigned long long g_ts[8];

// ---------------- helpers ----------------
__device__ __forceinline__ void ts_mark(int i) {
    if (blockIdx.x == 0 && blockIdx.y == 0 && threadIdx.x == 0) {
        unsigned long long t;
        asm volatile("mov.u64 %0, %%globaltimer;" : "=l"(t));
        g_ts[i] = t;
    }
}
__device__ __forceinline__ void mma_bf16(float* d, const uint32_t* a, const uint32_t* b) {
    asm volatile(
        "mma.sync.aligned.m16n8k16.row.col.f32.bf16.bf16.f32 "
        "{%0,%1,%2,%3}, {%4,%5,%6,%7}, {%8,%9}, {%0,%1,%2,%3};"
        : "+f"(d[0]), "+f"(d[1]), "+f"(d[2]), "+f"(d[3])
        : "r"(a[0]), "r"(a[1]), "r"(a[2]), "r"(a[3]), "r"(b[0]), "r"(b[1]));
}
__device__ __forceinline__ void split2(float x, float y, uint32_t& h, uint32_t& l) {
    __nv_bfloat16 hx = __float2bfloat16_rn(x);
    __nv_bfloat16 hy = __float2bfloat16_rn(y);
    __nv_bfloat16 lx = __float2bfloat16_rn(x - __bfloat162float(hx));
    __nv_bfloat16 ly = __float2bfloat16_rn(y - __bfloat162float(hy));
    __nv_bfloat162 ph = __halves2bfloat162(hx, hy);
    __nv_bfloat162 pl = __halves2bfloat162(lx, ly);
    h = *reinterpret_cast<uint32_t*>(&ph);
    l = *reinterpret_cast<uint32_t*>(&pl);
}

// ---------------- prep kernels ----------------
__global__ void init_kernel(const float* __restrict__ init_state) {
    ts_mark(0);
    int i = blockIdx.x * blockDim.x + threadIdx.x;
    if (i == 0) { g_cnt = 0u; g_flag = 0u; }
    if (i < 8) g_prog[i] = 0u;
    if (i < NN * BB) {
        int b = i & (BB - 1);
        int n = i >> 4;
        g_state0[i] = init_state[(size_t)b * NN + n];
    }
}

__global__ void count_kernel(const float* __restrict__ W) {
    ts_mark(1);
    int gw   = (blockIdx.x * blockDim.x + threadIdx.x) >> 5;
    int lane = threadIdx.x & 31;
    if (gw >= NN) return;
    const float* row = W + (size_t)gw * NN;
    int c = 0;
    for (int m0 = 0; m0 < NN; m0 += 32) {
        float w = row[m0 + lane];
        c += __popc(__ballot_sync(0xffffffffu, w != 0.0f));
    }
    if (lane == 0) g_nnz[gw] = (c + 15) & ~15;
}

__global__ void scan_kernel() {
    ts_mark(2);
    __shared__ int sb[2][NN];
    int t = threadIdx.x;
    sb[0][t] = g_nnz[t];
    sb[0][t + 1024] = g_nnz[t + 1024];
    __syncthreads();
    int cur = 0;
    for (int d = 1; d < NN; d <<= 1) {
        for (int k = t; k < NN; k += 1024) {
            int v = sb[cur][k];
            if (k >= d) v += sb[cur][k - d];
            sb[cur ^ 1][k] = v;
        }
        __syncthreads();
        cur ^= 1;
    }
    if (t == 0) g_rowptr[0] = 0;
    g_rowptr[t + 1] = sb[cur][t];
    g_rowptr[t + 1 + 1024] = sb[cur][t + 1024];
}

__global__ void fill_kernel(const float* __restrict__ W) {
    ts_mark(3);
    int gw   = (blockIdx.x * blockDim.x + threadIdx.x) >> 5;
    int lane = threadIdx.x & 31;
    if (gw >= NN) return;
    const float* row = W + (size_t)gw * NN;
    int p = g_rowptr[gw];
    for (int m0 = 0; m0 < NN; m0 += 32) {
        float w = row[m0 + lane];
        unsigned msk = __ballot_sync(0xffffffffu, w != 0.0f);
        if (w != 0.0f) {
            int off = p + __popc(msk & ((1u << lane) - 1u));
            g_ent[off] = make_float2(w, __int_as_float(m0 + lane));
        }
        p += __popc(msk);
    }
    int end = g_rowptr[gw + 1];
    for (int q = p + lane; q < end; q += 32)
        g_ent[q] = make_float2(0.0f, __int_as_float(0));
}

// ---------------- bf16 3-split mma.sync drive GEMM (s-chunk-major order) ----------------
#define SMU 20

__global__ void __launch_bounds__(256) drive_gemm_bf16(
    const float* __restrict__ X, const float* __restrict__ FB,
    const float* __restrict__ Win, const float* __restrict__ Wfb)
{
    ts_mark(4);
    __shared__ uint32_t Ah[128 * SMU], Al[128 * SMU], Bh[128 * SMU], Bl[128 * SMU];

    int tid  = threadIdx.x;
    int wid  = tid >> 5, lane = tid & 31;
    int gid  = lane >> 2, tig = lane & 3;
    int wm   = wid & 1, wn = wid >> 1;

    // s-chunk-major remap: y in [0,128) -> sChunk = y>>4, bIdx = y&15.
    // All 256 CTAs (16 bIdx x 16 col-tiles) of sChunk k occupy blockIdx range [k*256,(k+1)*256).
    int sChunk = blockIdx.y >> 4;
    int bIdx   = blockIdx.y & 15;
    int rowBase = bIdx * 1024 + sChunk * 128;
    int colBase = blockIdx.x * 128;

    int lr = tid >> 1;
    int lh = (tid & 1) * 4;

    const float* Aarr[2] = {X, FB};
    const float* Barr[2] = {Win, Wfb};

    float acc[4][4][4];
#pragma unroll
    for (int i = 0; i < 4; i++)
#pragma unroll
        for (int j = 0; j < 4; j++)
#pragma unroll
            for (int k = 0; k < 4; k++) acc[i][j][k] = 0.0f;

    float4 ra[4], rb[4];
#pragma unroll
    for (int j = 0; j < 4; j++) {
        ra[j] = __ldg((const float4*)(X   + (size_t)(rowBase + lr) * DD) + lh + j);
        rb[j] = __ldg((const float4*)(Win + (size_t)(colBase + lr) * DD) + lh + j);
    }

    const int NCHUNK = 32;
    for (int kt = 0; kt < NCHUNK; kt++) {
        __syncthreads();
#pragma unroll
        for (int j = 0; j < 4; j++) {
            int c4 = lh + j;
            int ui = lr * SMU + c4 * 2;
            uint32_t h0, l0, h1, l1;
            split2(ra[j].x, ra[j].y, h0, l0);
            split2(ra[j].z, ra[j].w, h1, l1);
            *(uint2*)&Ah[ui] = make_uint2(h0, h1);
            *(uint2*)&Al[ui] = make_uint2(l0, l1);
            split2(rb[j].x, rb[j].y, h0, l0);
            split2(rb[j].z, rb[j].w, h1, l1);
            *(uint2*)&Bh[ui] = make_uint2(h0, h1);
            *(uint2*)&Bl[ui] = make_uint2(l0, l1);
        }
        __syncthreads();

        if (kt + 1 < NCHUNK) {
            int nk = kt + 1;
            const float* A  = Aarr[nk >> 4];
            const float* Bm = Barr[nk >> 4];
            int kb = (nk & 15) * 8;
#pragma unroll
            for (int j = 0; j < 4; j++) {
                ra[j] = __ldg((const float4*)(A  + (size_t)(rowBase + lr) * DD) + kb + lh + j);
                rb[j] = __ldg((const float4*)(Bm + (size_t)(colBase + lr) * DD) + kb + lh + j);
            }
        }

#pragma unroll
        for (int ks = 0; ks < 2; ks++) {
            uint32_t bh[4][2], bl[4][2];
#pragma unroll
            for (int nt = 0; nt < 4; nt++) {
                int r = (wn * 32 + nt * 8 + gid) * SMU + ks * 8;
                bh[nt][0] = Bh[r + tig];
                bh[nt][1] = Bh[r + tig + 4];
                bl[nt][0] = Bl[r + tig];
                bl[nt][1] = Bl[r + tig + 4];
            }
#pragma unroll
            for (int mt = 0; mt < 4; mt++) {
                int r1 = (wm * 64 + mt * 16 + gid) * SMU + ks * 8;
                int r2 = r1 + 8 * SMU;
                uint32_t ah[4], al[4];
                ah[0] = Ah[r1 + tig]; ah[1] = Ah[r2 + tig];
                ah[2] = Ah[r1 + tig + 4]; ah[3] = Ah[r2 + tig + 4];
                al[0] = Al[r1 + tig]; al[1] = Al[r2 + tig];
                al[2] = Al[r1 + tig + 4]; al[3] = Al[r2 + tig + 4];
#pragma unroll
                for (int nt = 0; nt < 4; nt++) {
                    mma_bf16(acc[mt][nt], ah, bh[nt]);
                    mma_bf16(acc[mt][nt], ah, bl[nt]);
                    mma_bf16(acc[mt][nt], al, bh[nt]);
                }
            }
        }
    }

#pragma unroll
    for (int mt = 0; mt < 4; mt++) {
#pragma unroll
        for (int half = 0; half < 2; half++) {
            int m = rowBase + wm * 64 + mt * 16 + gid + half * 8;
            int b = m >> 10, s = m & 1023;
            size_t base = ((size_t)s * NN) * BB + b;
#pragma unroll
            for (int nt = 0; nt < 4; nt++) {
                int n = colBase + wn * 32 + nt * 8 + tig * 2;
                g_drive[base + (size_t)n * BB]       = acc[mt][nt][half * 2];
                g_drive[base + (size_t)(n + 1) * BB] = acc[mt][nt][half * 2 + 1];
            }
        }
    }

    // progress: this CTA's 128 s-values of chunk sChunk are written
    __threadfence();
    __syncthreads();
    if (tid == 0) atomicAdd(&g_prog[sChunk], 1u);
}

// ---------------- persistent recurrence (overlapped with GEMM) ----------------
__global__ void __launch_bounds__(RTHREADS, 1) recur_kernel() {
    ts_mark(5);
    int tid  = threadIdx.x;
    int w    = tid >> 5;
    int lane = tid & 31;
    int b    = lane & 15;
    int rsel = lane >> 4;
    int row  = blockIdx.x * (RTHREADS / 16) + w * 2 + rsel;

    int start = g_rowptr[row];
    int len   = g_rowptr[row + 1] - start;   // multiple of 16
    const float2* ent = g_ent + start;

    // wait for GEMM chunk 0
    if (tid == 0) {
        unsigned v;
        do {
            asm volatile("ld.acquire.gpu.global.u32 %0, [%1];"
                         : "=r"(v) : "l"(&g_prog[0]) : "memory");
        } while (v < 256u);
    }
    __syncthreads();

    const float* cur = g_state0;
    float drv = __ldcg(&g_drive[(row << 4) + b]);

    for (int s = 0; s < SS; ++s) {
        float acc = drv;
        for (int j = 0; j < len; j += 16) {
#pragma unroll
            for (int u = 0; u < 16; u++) {
                float2 e = ent[j + u];
                float sv = __ldcg(cur + ((__float_as_int(e.y) << 4) + b));
                acc = fmaf(e.x, sv, acc);
            }
        }
        float ns = tanhf(acc);
        float* d = g_drive + (size_t)s * (NN * BB);
        d[(row << 4) + b] = ns;

        bool cross = ((s + 1) & 127) == 0;       // next step enters a new GEMM chunk
        if (s + 1 < SS && !cross)                // prefetch next drive behind barrier
            drv = __ldcg(&g_drive[(size_t)(s + 1) * (NN * BB) + (row << 4) + b]);

        __syncthreads();
        if (s + 1 < SS) {
            if (tid == 0) {
                unsigned arr;
                asm volatile("atom.acq_rel.gpu.global.add.u32 %0, [%1], %2;"
                             : "=r"(arr) : "l"(&g_cnt), "r"(1u) : "memory");
                unsigned target = (unsigned)RCTAS * (unsigned)(s + 1);
                if (arr == target - 1u) {
                    asm volatile("st.release.gpu.global.u32 [%0], %1;"
                                 :: "l"(&g_flag), "r"((unsigned)(s + 1)) : "memory");
                } else {
                    unsigned v;
                    do {
                        asm volatile("ld.acquire.gpu.global.u32 %0, [%1];"
                                     : "=r"(v) : "l"(&g_flag) : "memory");
                    } while (v < (unsigned)(s + 1));
                }
                if (cross) {   // rare (7x): wait for GEMM to finish next chunk
                    unsigned v;
                    do {
                        asm volatile("ld.acquire.gpu.global.u32 %0, [%1];"
                                     : "=r"(v) : "l"(&g_prog[(s + 1) >> 7]) : "memory");
                    } while (v < 256u);
                }
            }
            __syncthreads();
            if (cross)
                drv = __ldcg(&g_drive[(size_t)(s + 1) * (NN * BB) + (row << 4) + b]);
        }
        cur = d;
    }
}

// ---------------- final transpose: g_drive[s][n][b] -> out[b][s][n] ----------------
#define TSB 8
#define TNB 64
__global__ void __launch_bounds__(256) transpose_kernel(float* __restrict__ out) {
    ts_mark(6);
    __shared__ float smt[TSB * TNB * 17];
    int s0 = blockIdx.y * TSB, n0 = blockIdx.x * TNB;
    for (int i = threadIdx.x; i < TSB * TNB * BB; i += 256) {
        int b = i & 15, nl = (i >> 4) & 63, sl = i >> 10;
        smt[(sl * TNB + nl) * 17 + b] =
            g_drive[((size_t)(s0 + sl) * NN + n0 + nl) * BB + b];
    }
    __syncthreads();
    for (int i = threadIdx.x; i < TSB * TNB * BB; i += 256) {
        int nl = i & 63, sl = (i >> 6) & 7, b = i >> 9;
        out[((size_t)b * SS + s0 + sl) * NN + n0 + nl] =
            smt[(sl * TNB + nl) * 17 + b];
    }
}

// ---------------- timing reporter ----------------
__global__ void report_kernel() {
    unsigned long long t;
    asm volatile("mov.u64 %0, %%globaltimer;" : "=l"(t));
    g_ts[7] = t;
    unsigned long long* ts = g_ts;
    printf("KTIME(us) init=%llu count=%llu scan=%llu fill=%llu gemm_start_to_recur_start=%llu recur_to_trans=%llu trans=%llu\n",
           (ts[1] - ts[0]) / 1000ull, (ts[2] - ts[1]) / 1000ull,
           (ts[3] - ts[2]) / 1000ull, (ts[4] - ts[3]) / 1000ull,
           (ts[5] - ts[4]) / 1000ull, (ts[6] - ts[5]) / 1000ull,
           (ts[7] - ts[6]) / 1000ull);
}

// ---------------- launch ----------------
extern "C" void kernel_launch(void* const* d_in, const int* in_sizes, int n_in,
                              void* d_out, int out_size) {
    const float* x    = (const float*)d_in[0];
    const float* fb   = (const float*)d_in[1];
    const float* init = (const float*)d_in[2];
    const float* Wres = (const float*)d_in[3];
    const float* Win  = (const float*)d_in[4];
    const float* Wfb  = (const float*)d_in[5];
    float* out = (float*)d_out;

    // Lazily created on the first (non-captured, correctness) call; reused during capture.
    static cudaStream_t side = nullptr;
    static cudaEvent_t ev_fork = nullptr, ev_join = nullptr;
    if (side == nullptr) {
        cudaStreamCreateWithFlags(&side, cudaStreamNonBlocking);
        cudaEventCreateWithFlags(&ev_fork, cudaEventDisableTiming);
        cudaEventCreateWithFlags(&ev_join, cudaEventDisableTiming);
    }

    init_kernel<<<(NN * BB + 255) / 256, 256>>>(init);
    count_kernel<<<64, 1024>>>(Wres);
    scan_kernel<<<1, 1024>>>();
    fill_kernel<<<64, 1024>>>(Wres);

    // fork: recurrence runs on side stream, overlapping the GEMM on the main stream
    cudaEventRecord(ev_fork, 0);
    cudaStreamWaitEvent(side, ev_fork, 0);
    recur_kernel<<<RCTAS, RTHREADS, 0, side>>>();
    cudaEventRecord(ev_join, side);

    drive_gemm_bf16<<<dim3(NN / 128, 128), 256>>>(x, fb, Win, Wfb);

    // join: transpose needs both GEMM (program order) and recurrence (event) done
    cudaStreamWaitEvent(0, ev_join, 0);
    transpose_kernel<<<dim3(NN / TNB, SS / TSB), 256>>>(out);
    report_kernel<<<1, 1>>>();
}